// round 8
// baseline (speedup 1.0000x reference)
#include <cuda_runtime.h>
#include <cuda_bf16.h>
#include <math.h>
#include <stdint.h>

// Problem constants
#define BB 2
#define SS 2048
#define DD 2048
#define NH 32
#define NKV 8
#define HD 64
#define GG 4

#define GKP 6144          // split-K: 3 x 2048
#define NCH64 96          // 6144 / 64

// ---------------------------------------------------------------------------
// Scratch buffers
// ---------------------------------------------------------------------------
__device__ __nv_bfloat16 g_xs[BB * SS * GKP];          // x split (hi,hi,lo)
__device__ __nv_bfloat16 g_os[BB * SS * GKP];          // attn out split (hi,hi,lo)
__device__ __nv_bfloat16 g_wqkvs[3072 * GKP];          // [wq;wk;wv] split (hi,lo,hi)
__device__ __nv_bfloat16 g_wos[DD * GKP];

__device__ __nv_bfloat16 g_Q3[BB * NH * SS * 192];     // [b][h][s][qh|ql|qh] (scaled)
__device__ __nv_bfloat16 g_K3[BB * NKV * SS * 192];    // [b][kh][s][kh|kh|kl]
__device__ __nv_bfloat16 g_Vt[BB * NKV * 2 * HD * SS]; // [b][kh][plane][d][s]

// ---------------------------------------------------------------------------
__device__ __forceinline__ uint32_t smem_u32(const void* p) {
    uint32_t a;
    asm("{ .reg .u64 t; cvta.to.shared.u64 t, %1; cvt.u32.u64 %0, t; }"
        : "=r"(a) : "l"(p));
    return a;
}
__device__ __forceinline__ void cpa16(uint32_t s, const void* g) {
    asm volatile("cp.async.cg.shared.global [%0], [%1], 16;" :: "r"(s), "l"(g));
}
__device__ __forceinline__ void cpcommit() { asm volatile("cp.async.commit_group;"); }
__device__ __forceinline__ void cpwait0() { asm volatile("cp.async.wait_group 0;"); }
__device__ __forceinline__ void cpwait1() { asm volatile("cp.async.wait_group 1;"); }
__device__ __forceinline__ void ldsm4(uint32_t* r, uint32_t addr) {
    asm volatile("ldmatrix.sync.aligned.m8n8.x4.shared.b16 {%0,%1,%2,%3}, [%4];"
                 : "=r"(r[0]), "=r"(r[1]), "=r"(r[2]), "=r"(r[3]) : "r"(addr));
}
__device__ __forceinline__ void mma16816(float* d, const uint32_t* a, const uint32_t* b) {
    asm volatile(
        "mma.sync.aligned.m16n8k16.row.col.f32.bf16.bf16.f32 "
        "{%0,%1,%2,%3}, {%4,%5,%6,%7}, {%8,%9}, {%0,%1,%2,%3};"
        : "+f"(d[0]), "+f"(d[1]), "+f"(d[2]), "+f"(d[3])
        : "r"(a[0]), "r"(a[1]), "r"(a[2]), "r"(a[3]), "r"(b[0]), "r"(b[1]));
}
__device__ __forceinline__ void split2(float v0, float v1,
                                       __nv_bfloat162& hi, __nv_bfloat162& lo) {
    __nv_bfloat16 h0 = __float2bfloat16(v0), h1 = __float2bfloat16(v1);
    hi.x = h0; hi.y = h1;
    lo.x = __float2bfloat16(v0 - __bfloat162float(h0));
    lo.y = __float2bfloat16(v1 - __bfloat162float(h1));
}
__device__ __forceinline__ void split_pack(float a, float b,
                                           uint32_t& hi, uint32_t& lo) {
    __nv_bfloat162 h, l;
    split2(a, b, h, l);
    hi = *(uint32_t*)&h; lo = *(uint32_t*)&l;
}

// ---------------------------------------------------------------------------
// Split kernels: fp32 [rows,2048] -> bf16 [rows,6144]
// ---------------------------------------------------------------------------
__global__ void split_hhl(const float* __restrict__ in,
                          __nv_bfloat16* __restrict__ out, int rows) {
    int idx = blockIdx.x * 256 + threadIdx.x;
    if (idx >= rows * 2048) return;
    int r = idx >> 11, c = idx & 2047;
    float v = in[idx];
    __nv_bfloat16 h = __float2bfloat16(v);
    __nv_bfloat16 l = __float2bfloat16(v - __bfloat162float(h));
    size_t o = (size_t)r * GKP + c;
    out[o] = h; out[o + 2048] = h; out[o + 4096] = l;
}

__global__ void split_hlh(const float* __restrict__ in,
                          __nv_bfloat16* __restrict__ out, int rows) {
    int idx = blockIdx.x * 256 + threadIdx.x;
    if (idx >= rows * 2048) return;
    int r = idx >> 11, c = idx & 2047;
    float v = in[idx];
    __nv_bfloat16 h = __float2bfloat16(v);
    __nv_bfloat16 l = __float2bfloat16(v - __bfloat162float(h));
    size_t o = (size_t)r * GKP + c;
    out[o] = h; out[o + 2048] = l; out[o + 4096] = h;
}

// ---------------------------------------------------------------------------
// GEMM mainloop (128x128x64 chunks, 4 warps 2x2, warp 64x64, 3 stages)
// ---------------------------------------------------------------------------
#define SKW_B 144                  // 64 bf16 = 128B data + 16B pad
#define GA_TILE (128 * SKW_B)      // 18432
#define GSTAGE  (2 * GA_TILE)      // 36864
#define GEMM_SMEM (3 * GSTAGE)     // 110592

#define GEMM_PROLOG(Abuf, Bbuf)                                               \
    extern __shared__ __align__(128) char smem[];                             \
    const uint32_t sb = smem_u32(smem);                                       \
    const int t = threadIdx.x;                                                \
    const int wid = t >> 5;                                                   \
    const int lane = t & 31;                                                  \
    const int wm = wid & 1;                                                   \
    const int wn = wid >> 1;                                                  \
    const int m0 = blockIdx.y * 128;                                          \
    const int n0 = blockIdx.x * 128;                                          \
    uint32_t soff[8];                                                         \
    const __nv_bfloat16* ag[8];                                               \
    const __nv_bfloat16* bg[8];                                               \
    _Pragma("unroll")                                                         \
    for (int i = 0; i < 8; i++) {                                             \
        int s = t + 128 * i;                                                  \
        int r = s >> 3, sg = s & 7;                                           \
        soff[i] = (uint32_t)(r * SKW_B + sg * 16);                            \
        ag[i] = (Abuf) + (size_t)(m0 + r) * GKP + sg * 8;                     \
        bg[i] = (Bbuf) + (size_t)(n0 + r) * GKP + sg * 8;                     \
    }                                                                         \
    const int aRow = (lane & 7) + (lane & 8);                                 \
    const uint32_t aColB = (lane & 16) ? 16u : 0u;                            \
    const int bRow = (lane & 7) + ((lane & 16) ? 8 : 0);                      \
    const uint32_t bColB = (lane & 8) ? 16u : 0u;                             \
    float acc[4][8][4];                                                       \
    _Pragma("unroll")                                                         \
    for (int i = 0; i < 4; i++)                                               \
        _Pragma("unroll")                                                     \
        for (int j = 0; j < 8; j++)                                           \
            _Pragma("unroll")                                                 \
            for (int r = 0; r < 4; r++) acc[i][j][r] = 0.f;                   \
    _Pragma("unroll")                                                         \
    for (int st = 0; st < 2; st++) {                                          \
        const uint32_t so = sb + st * GSTAGE;                                 \
        const int ko = st * 64;                                               \
        _Pragma("unroll")                                                     \
        for (int i = 0; i < 8; i++) {                                         \
            cpa16(so + soff[i], ag[i] + ko);                                  \
            cpa16(so + GA_TILE + soff[i], bg[i] + ko);                        \
        }                                                                     \
        cpcommit();                                                           \
    }                                                                         \
    for (int ch = 0; ch < NCH64; ch++) {                                      \
        if (ch + 1 < NCH64) cpwait1(); else cpwait0();                        \
        __syncthreads();                                                      \
        if (ch + 2 < NCH64) {                                                 \
            const uint32_t so = sb + ((ch + 2) % 3) * GSTAGE;                 \
            const int ko = (ch + 2) * 64;                                     \
            _Pragma("unroll")                                                 \
            for (int i = 0; i < 8; i++) {                                     \
                cpa16(so + soff[i], ag[i] + ko);                              \
                cpa16(so + GA_TILE + soff[i], bg[i] + ko);                    \
            }                                                                 \
            cpcommit();                                                       \
        }                                                                     \
        const uint32_t Ab = sb + (ch % 3) * GSTAGE;                           \
        const uint32_t Bb = Ab + GA_TILE;                                     \
        const uint32_t aBase = Ab + (uint32_t)(wm * 64 + aRow) * SKW_B + aColB;\
        const uint32_t bBase = Bb + (uint32_t)(wn * 64 + bRow) * SKW_B + bColB;\
        _Pragma("unroll")                                                     \
        for (int ks = 0; ks < 4; ks++) {                                      \
            uint32_t a[4][4];                                                 \
            uint32_t b[8][2];                                                 \
            _Pragma("unroll")                                                 \
            for (int i = 0; i < 4; i++)                                       \
                ldsm4(a[i], aBase + (uint32_t)(i * 16) * SKW_B + ks * 32);    \
            _Pragma("unroll")                                                 \
            for (int j2 = 0; j2 < 4; j2++) {                                  \
                uint32_t tmp[4];                                              \
                ldsm4(tmp, bBase + (uint32_t)(j2 * 16) * SKW_B + ks * 32);    \
                b[2 * j2][0] = tmp[0]; b[2 * j2][1] = tmp[1];                 \
                b[2 * j2 + 1][0] = tmp[2]; b[2 * j2 + 1][1] = tmp[3];         \
            }                                                                 \
            _Pragma("unroll")                                                 \
            for (int i = 0; i < 4; i++)                                       \
                _Pragma("unroll")                                             \
                for (int j = 0; j < 8; j++)                                   \
                    mma16816(acc[i][j], a[i], b[j]);                          \
        }                                                                     \
    }

// ---------------------------------------------------------------------------
// O-projection GEMM: fp32 C = A.B^T + bias
// ---------------------------------------------------------------------------
__global__ __launch_bounds__(128, 2)
void gemm_mma(const __nv_bfloat16* __restrict__ A,
              const __nv_bfloat16* __restrict__ Bm,
              const float* __restrict__ bias,
              float* __restrict__ C, int N) {
    GEMM_PROLOG(A, Bm)

#pragma unroll
    for (int i = 0; i < 4; i++) {
        const int r0 = m0 + wm * 64 + i * 16 + (lane >> 2);
#pragma unroll
        for (int j = 0; j < 8; j++) {
            const int c = n0 + wn * 64 + j * 8 + (lane & 3) * 2;
            const float b0 = bias[c], b1 = bias[c + 1];
            *(float2*)(C + (size_t)r0 * N + c) =
                make_float2(acc[i][j][0] + b0, acc[i][j][1] + b1);
            *(float2*)(C + (size_t)(r0 + 8) * N + c) =
                make_float2(acc[i][j][2] + b0, acc[i][j][3] + b1);
        }
    }
}

// ---------------------------------------------------------------------------
// Fused QKV GEMM -> attention-format outputs
// ---------------------------------------------------------------------------
__global__ __launch_bounds__(128, 2)
void gemm_qkv(const __nv_bfloat16* __restrict__ A,
              const __nv_bfloat16* __restrict__ Bm,
              const float* __restrict__ bq,
              const float* __restrict__ bk,
              const float* __restrict__ bv,
              __nv_bfloat16* __restrict__ Q3,
              __nv_bfloat16* __restrict__ K3,
              __nv_bfloat16* __restrict__ Vt) {
    GEMM_PROLOG(A, Bm)

    const int mode = (blockIdx.x < 16) ? 0 : (blockIdx.x < 20 ? 1 : 2);
    const float* bias = (mode == 0) ? bq : (mode == 1 ? bk : bv);
    const int creg0 = (mode == 0) ? 0 : (mode == 1 ? 2048 : 2560);

#pragma unroll
    for (int i = 0; i < 4; i++) {
#pragma unroll
        for (int rr = 0; rr < 2; rr++) {
            const int row = m0 + wm * 64 + i * 16 + (lane >> 2) + rr * 8;
            const int b = row >> 11, s = row & 2047;
#pragma unroll
            for (int j = 0; j < 8; j++) {
                const int cb = n0 + wn * 64 + j * 8 + (lane & 3) * 2 - creg0;
                const int hh = cb >> 6;
                const int d = cb & 63;
                float v0 = acc[i][j][rr * 2 + 0] + bias[cb];
                float v1 = acc[i][j][rr * 2 + 1] + bias[cb + 1];
                if (mode == 0) { v0 *= 0.125f; v1 *= 0.125f; }
                __nv_bfloat162 hi, lo;
                split2(v0, v1, hi, lo);
                if (mode == 0) {
                    __nv_bfloat16* base =
                        Q3 + ((size_t)(b * NH + hh) * SS + s) * 192 + d;
                    *(__nv_bfloat162*)(base) = hi;
                    *(__nv_bfloat162*)(base + 64) = lo;
                    *(__nv_bfloat162*)(base + 128) = hi;
                } else if (mode == 1) {
                    __nv_bfloat16* base =
                        K3 + ((size_t)(b * NKV + hh) * SS + s) * 192 + d;
                    *(__nv_bfloat162*)(base) = hi;
                    *(__nv_bfloat162*)(base + 64) = hi;
                    *(__nv_bfloat162*)(base + 128) = lo;
                } else {
                    __nv_bfloat16* base =
                        Vt + (((size_t)(b * NKV + hh) * 2) * HD + d) * SS + s;
                    base[0] = hi.x;
                    base[SS] = hi.y;
                    base[HD * SS] = lo.x;
                    base[HD * SS + SS] = lo.y;
                }
            }
        }
    }
}

// ---------------------------------------------------------------------------
// Tensor-core flash attention, row-per-warp, P in registers.
// 8 warps x 16 Q-rows; all 64 keys per warp; warp-local softmax.
// ---------------------------------------------------------------------------
#define AT_QS   0u
#define AT_ST0  51200u          // Q: 128 rows * 400B
#define AT_STSZ 44032u          // K 64*400 + V 2*64*144
#define AT_VOFF 25600u
#define AT_SMEM 183296          // 51200 + 3*44032

__global__ __launch_bounds__(256, 1)
void attn_mma(const __nv_bfloat16* __restrict__ Q3,
              const __nv_bfloat16* __restrict__ K3,
              const __nv_bfloat16* __restrict__ Vt,
              __nv_bfloat16* __restrict__ Os) {
    const int qtile = gridDim.x - 1 - blockIdx.x;   // longest first
    const int h = blockIdx.y;
    const int b = blockIdx.z;
    const int kh = h >> 2;
    const int q0 = qtile * 128;
    const int nkt = 2 * qtile + 2;

    extern __shared__ __align__(1024) char smem[];
    const uint32_t sb = smem_u32(smem);
    const int t = threadIdx.x;
    const int w = t >> 5;        // warp owns Q rows [w*16, w*16+16)
    const int lane = t & 31;

    const int aRow = (lane & 7) + (lane & 8);
    const uint32_t aColB = (lane & 16) ? 16u : 0u;
    const int bRow = (lane & 7) + ((lane & 16) ? 8 : 0);
    const uint32_t bColB = (lane & 8) ? 16u : 0u;

    const __nv_bfloat16* Qg = Q3 + ((size_t)(b * NH + h) * SS + q0) * 192;
    const __nv_bfloat16* Kg = K3 + (size_t)(b * NKV + kh) * SS * 192;
    const __nv_bfloat16* Vg = Vt + (size_t)(b * NKV + kh) * 2 * HD * SS;

    // ---- prologue: Q + stage0 (group 0), stage1 (group 1) ----
#pragma unroll
    for (int i = 0; i < 12; i++) {
        int sg = t + 256 * i;
        int r = sg / 24, c = sg % 24;
        cpa16(sb + AT_QS + r * 400 + c * 16, Qg + (size_t)r * 192 + c * 8);
    }
    {
        const uint32_t so = sb + AT_ST0;
#pragma unroll
        for (int i = 0; i < 6; i++) {
            int sg = t + 256 * i;
            int r = sg / 24, c = sg % 24;
            cpa16(so + r * 400 + c * 16, Kg + (size_t)r * 192 + c * 8);
        }
#pragma unroll
        for (int i = 0; i < 4; i++) {
            int sg = t + 256 * i;
            int p = sg >> 9, d = (sg >> 3) & 63, c = sg & 7;
            cpa16(so + AT_VOFF + p * 9216 + d * 144 + c * 16,
                  Vg + ((size_t)(p * HD + d)) * SS + c * 8);
        }
    }
    cpcommit();
    {
        const uint32_t so = sb + AT_ST0 + AT_STSZ;
#pragma unroll
        for (int i = 0; i < 6; i++) {
            int sg = t + 256 * i;
            int r = sg / 24, c = sg % 24;
            cpa16(so + r * 400 + c * 16, Kg + (size_t)(64 + r) * 192 + c * 8);
        }
#pragma unroll
        for (int i = 0; i < 4; i++) {
            int sg = t + 256 * i;
            int p = sg >> 9, d = (sg >> 3) & 63, c = sg & 7;
            cpa16(so + AT_VOFF + p * 9216 + d * 144 + c * 16,
                  Vg + ((size_t)(p * HD + d)) * SS + 64 + c * 8);
        }
    }
    cpcommit();

    // ---- hoist Q fragments into registers (group 0 must be complete) ----
    cpwait1();
    __syncthreads();
    uint32_t qf[12][4];
    {
        const uint32_t aQ = sb + AT_QS + (uint32_t)(w * 16 + aRow) * 400 + aColB;
#pragma unroll
        for (int ks = 0; ks < 12; ks++)
            ldsm4(qf[ks], aQ + ks * 32);
    }

    float acc_o[8][4];
#pragma unroll
    for (int j = 0; j < 8; j++)
#pragma unroll
        for (int r = 0; r < 4; r++) acc_o[j][r] = 0.f;
    float m0s = -1e30f, m1s = -1e30f, l0s = 0.f, l1s = 0.f;

    for (int kt = 0; kt < nkt; kt++) {
        if (kt + 1 < nkt) cpwait1(); else cpwait0();
        __syncthreads();

        if (kt + 2 < nkt) {
            const uint32_t so = sb + AT_ST0 + ((kt + 2) % 3) * AT_STSZ;
            const int k0 = (kt + 2) * 64;
#pragma unroll
            for (int i = 0; i < 6; i++) {
                int sg = t + 256 * i;
                int r = sg / 24, c = sg % 24;
                cpa16(so + r * 400 + c * 16, Kg + (size_t)(k0 + r) * 192 + c * 8);
            }
#pragma unroll
            for (int i = 0; i < 4; i++) {
                int sg = t + 256 * i;
                int p = sg >> 9, d = (sg >> 3) & 63, c = sg & 7;
                cpa16(so + AT_VOFF + p * 9216 + d * 144 + c * 16,
                      Vg + ((size_t)(p * HD + d)) * SS + k0 + c * 8);
            }
            cpcommit();
        }

        const uint32_t stOff = sb + AT_ST0 + (kt % 3) * AT_STSZ;

        // ---- scores: 16 rows x 64 keys, 3-term split over 192 ----
        float s[8][4];
#pragma unroll
        for (int j = 0; j < 8; j++)
#pragma unroll
            for (int r = 0; r < 4; r++) s[j][r] = 0.f;

        const uint32_t bK = stOff + (uint32_t)bRow * 400 + bColB;
#pragma unroll
        for (int ks = 0; ks < 12; ks++) {
            uint32_t bb[8][2];
#pragma unroll
            for (int j2 = 0; j2 < 4; j2++) {
                uint32_t tmp[4];
                ldsm4(tmp, bK + (uint32_t)(j2 * 16) * 400 + ks * 32);
                bb[2 * j2][0] = tmp[0]; bb[2 * j2][1] = tmp[1];
                bb[2 * j2 + 1][0] = tmp[2]; bb[2 * j2 + 1][1] = tmp[3];
            }
#pragma unroll
            for (int j = 0; j < 8; j++)
                mma16816(s[j], qf[ks], bb[j]);
        }

        // ---- causal mask (diagonal tiles only) ----
        if (kt >= 2 * qtile) {
            const int row0 = q0 + w * 16 + (lane >> 2);
#pragma unroll
            for (int j = 0; j < 8; j++)
#pragma unroll
                for (int r = 0; r < 4; r++) {
                    int col = kt * 64 + j * 8 + (lane & 3) * 2 + (r & 1);
                    int row = row0 + (r >> 1) * 8;
                    if (col > row) s[j][r] = -1e30f;
                }
        }

        // ---- warp-local row max ----
        float mx0 = -1e30f, mx1 = -1e30f;
#pragma unroll
        for (int j = 0; j < 8; j++) {
            mx0 = fmaxf(mx0, fmaxf(s[j][0], s[j][1]));
            mx1 = fmaxf(mx1, fmaxf(s[j][2], s[j][3]));
        }
        mx0 = fmaxf(mx0, __shfl_xor_sync(0xffffffffu, mx0, 1));
        mx0 = fmaxf(mx0, __shfl_xor_sync(0xffffffffu, mx0, 2));
        mx1 = fmaxf(mx1, __shfl_xor_sync(0xffffffffu, mx1, 1));
        mx1 = fmaxf(mx1, __shfl_xor_sync(0xffffffffu, mx1, 2));

        const float mn0 = fmaxf(m0s, mx0);
        const float mn1 = fmaxf(m1s, mx1);
        const float al0 = __expf(m0s - mn0);
        const float al1 = __expf(m1s - mn1);
        m0s = mn0; m1s = mn1;

#pragma unroll
        for (int j = 0; j < 8; j++) {
            acc_o[j][0] *= al0; acc_o[j][1] *= al0;
            acc_o[j][2] *= al1; acc_o[j][3] *= al1;
        }

        // ---- exp -> P fragments in registers (hi + lo planes) ----
        uint32_t Ph[4][4], Pl[4][4];
        float sum0 = 0.f, sum1 = 0.f;
#pragma unroll
        for (int j = 0; j < 8; j++) {
            float p0 = __expf(s[j][0] - mn0);
            float p1 = __expf(s[j][1] - mn0);
            float p2 = __expf(s[j][2] - mn1);
            float p3 = __expf(s[j][3] - mn1);
            sum0 += p0 + p1;
            sum1 += p2 + p3;
            const int ks = j >> 1, hf = (j & 1) * 2;
            split_pack(p0, p1, Ph[ks][hf + 0], Pl[ks][hf + 0]);
            split_pack(p2, p3, Ph[ks][hf + 1], Pl[ks][hf + 1]);
        }
        // NOTE: A-frag order is a0=(row,k0),a1=(row+8,k0),a2=(row,k8),a3=(row+8,k8):
        // j even -> a0,a1 ; j odd -> a2,a3. hf mapping above gives [0]=p0p1(row),
        // [1]=p2p3(row+8) for even j and [2],[3] for odd j. Correct.
        sum0 += __shfl_xor_sync(0xffffffffu, sum0, 1);
        sum0 += __shfl_xor_sync(0xffffffffu, sum0, 2);
        sum1 += __shfl_xor_sync(0xffffffffu, sum1, 1);
        sum1 += __shfl_xor_sync(0xffffffffu, sum1, 2);
        l0s = l0s * al0 + sum0;
        l1s = l1s * al1 + sum1;

        // ---- PV: 3 passes (Ph*Vh, Pl*Vh, Ph*Vl) ----
#pragma unroll
        for (int pass = 0; pass < 3; pass++) {
            const uint32_t plane = (pass == 2) ? 1u : 0u;
            const uint32_t bV = stOff + AT_VOFF + plane * 9216 +
                                (uint32_t)bRow * 144 + bColB;
#pragma unroll
            for (int ks = 0; ks < 4; ks++) {
                uint32_t bb[8][2];
#pragma unroll
                for (int j2 = 0; j2 < 4; j2++) {
                    uint32_t tmp[4];
                    ldsm4(tmp, bV + (uint32_t)(j2 * 16) * 144 + ks * 32);
                    bb[2 * j2][0] = tmp[0]; bb[2 * j2][1] = tmp[1];
                    bb[2 * j2 + 1][0] = tmp[2]; bb[2 * j2 + 1][1] = tmp[3];
                }
                const uint32_t* ap = (pass == 1) ? Pl[ks] : Ph[ks];
#pragma unroll
                for (int j = 0; j < 8; j++)
                    mma16816(acc_o[j], ap, bb[j]);
            }
        }
    }

    // ---- epilogue: normalize + write split-hhl rows of g_os ----
    const float inv0 = 1.f / l0s;
    const float inv1 = 1.f / l1s;
#pragma unroll
    for (int ri = 0; ri < 2; ri++) {
        const float inv = ri ? inv1 : inv0;
        const int srow = q0 + w * 16 + (lane >> 2) + ri * 8;
        __nv_bfloat16* orow = Os + (size_t)(b * SS + srow) * GKP;
#pragma unroll
        for (int j = 0; j < 8; j++) {
            const int col = h * HD + j * 8 + (lane & 3) * 2;
            float v0 = acc_o[j][ri * 2] * inv;
            float v1 = acc_o[j][ri * 2 + 1] * inv;
            __nv_bfloat162 hi, lo;
            split2(v0, v1, hi, lo);
            *(__nv_bfloat162*)(orow + col) = hi;
            *(__nv_bfloat162*)(orow + col + 2048) = hi;
            *(__nv_bfloat162*)(orow + col + 4096) = lo;
        }
    }
}

// ---------------------------------------------------------------------------
extern "C" void kernel_launch(void* const* d_in, const int* in_sizes, int n_in,
                              void* d_out, int out_size) {
    (void)in_sizes; (void)n_in; (void)out_size;
    const float* x  = (const float*)d_in[0];
    const float* wq = (const float*)d_in[1];
    const float* bq = (const float*)d_in[2];
    const float* wk = (const float*)d_in[3];
    const float* bk = (const float*)d_in[4];
    const float* wv = (const float*)d_in[5];
    const float* bv = (const float*)d_in[6];
    const float* wo = (const float*)d_in[7];
    const float* bo = (const float*)d_in[8];
    float* out = (float*)d_out;

    __nv_bfloat16 *xs, *os, *wqkvs, *wos, *q3, *k3, *vt;
    cudaGetSymbolAddress((void**)&xs,    g_xs);
    cudaGetSymbolAddress((void**)&os,    g_os);
    cudaGetSymbolAddress((void**)&wqkvs, g_wqkvs);
    cudaGetSymbolAddress((void**)&wos,   g_wos);
    cudaGetSymbolAddress((void**)&q3,    g_Q3);
    cudaGetSymbolAddress((void**)&k3,    g_K3);
    cudaGetSymbolAddress((void**)&vt,    g_Vt);

    const int M = BB * SS;  // 4096
    cudaFuncSetAttribute(gemm_mma, cudaFuncAttributeMaxDynamicSharedMemorySize,
                         GEMM_SMEM);
    cudaFuncSetAttribute(gemm_qkv, cudaFuncAttributeMaxDynamicSharedMemorySize,
                         GEMM_SMEM);
    cudaFuncSetAttribute(attn_mma, cudaFuncAttributeMaxDynamicSharedMemorySize,
                         AT_SMEM);

    // Splits: x (hhl), weights (hlh; wq/wk/wv packed)
    split_hhl<<<(M * 2048 + 255) / 256, 256>>>(x, xs, M);
    split_hlh<<<(2048 * 2048 + 255) / 256, 256>>>(wq, wqkvs, 2048);
    split_hlh<<<(512 * 2048 + 255) / 256, 256>>>(wk, wqkvs + (size_t)2048 * GKP, 512);
    split_hlh<<<(512 * 2048 + 255) / 256, 256>>>(wv, wqkvs + (size_t)2560 * GKP, 512);
    split_hlh<<<(2048 * 2048 + 255) / 256, 256>>>(wo, wos, 2048);

    // Fused QKV projection -> attention formats
    dim3 gqkv(3072 / 128, M / 128);
    gemm_qkv<<<gqkv, 128, GEMM_SMEM>>>(xs, wqkvs, bq, bk, bv, q3, k3, vt);

    // Attention
    dim3 ga(SS / 128, NH, BB);
    attn_mma<<<ga, 256, AT_SMEM>>>(q3, k3, vt, os);

    // Output projection
    dim3 gq(2048 / 128, M / 128);
    gemm_mma<<<gq, 128, GEMM_SMEM>>>(os, wos, bo, out, 2048);
}